// round 16
// baseline (speedup 1.0000x reference)
#include <cuda_runtime.h>
#include <cuda_bf16.h>
#include <math.h>
#include <stdint.h>

// ---------------------------------------------------------------------------
// GatedDeltaNet forward, GB300 (sm_103a bench; legacy PTX target => warp MMA).
// GEMMs: TF32 m16n8k8 (R12 proven, HMMA rate-capped). Non-GEMM kernels tuned.
// Shapes: B=2, S=4096, D=2048, H=16, DK=DV=128, CONV_DIM=6144, KCONV=4
// ---------------------------------------------------------------------------

#define BDIM   2
#define SDIM   4096
#define DDIM   2048
#define HN     16
#define DKN    128
#define CONVD  6144
#define KEYD   2048
#define VALD   2048
#define NPOS   (BDIM*SDIM)        // 8192
#define EPSF   1e-6f

// ---- scratch (device global; allocation-free) ----
#define OFF_MIXED 0
#define OFF_Z     50331648
#define OFF_Q     67108864
#define OFF_K     83886080
#define OFF_V     100663296
#define OFF_CORE  117440512
#define OFF_EG    134217728
#define OFF_BETA  134348800
#define SCRATCH_TOTAL 134479872

__device__ float g_scratch[SCRATCH_TOTAL];

// ---------------------------------------------------------------------------
// TF32 helpers
// ---------------------------------------------------------------------------
__device__ __forceinline__ float f2tf32(float x) {
    uint32_t u;
    asm("cvt.rna.tf32.f32 %0, %1;" : "=r"(u) : "f"(x));
    return __uint_as_float(u);
}
__device__ __forceinline__ float4 f2tf32x4(float4 v) {
    return make_float4(f2tf32(v.x), f2tf32(v.y), f2tf32(v.z), f2tf32(v.w));
}
__device__ __forceinline__ void mma_tf32(float* c, const uint32_t* a,
                                         uint32_t b0, uint32_t b1) {
    asm volatile(
        "mma.sync.aligned.m16n8k8.row.col.f32.tf32.tf32.f32 "
        "{%0,%1,%2,%3}, {%4,%5,%6,%7}, {%8,%9}, {%0,%1,%2,%3};"
        : "+f"(c[0]), "+f"(c[1]), "+f"(c[2]), "+f"(c[3])
        : "r"(a[0]), "r"(a[1]), "r"(a[2]), "r"(a[3]), "r"(b0), "r"(b1));
}

// ---------------------------------------------------------------------------
// TF32 GEMM (verbatim from R12, best known): 128x128 tile, BK=16, 256 thr.
// ---------------------------------------------------------------------------
__global__ __launch_bounds__(256, 2)
void gemm_tf32_kernel(const float* __restrict__ A, const float* __restrict__ B,
                      float* __restrict__ C, int M, int N, int K) {
    __shared__ __align__(16) float As[2][128][20];
    __shared__ __align__(16) float Bs[2][16][136];

    const int tid  = threadIdx.x;
    const int bm   = blockIdx.y * 128;
    const int bn   = blockIdx.x * 128;

    const int warp = tid >> 5, lane = tid & 31;
    const int wm = (warp & 3) * 32;
    const int wn = (warp >> 2) * 64;
    const int g  = lane >> 2;
    const int tig = lane & 3;

    const int ar = tid >> 2;
    const int ac = (tid & 3) << 2;
    const int br = tid >> 5;
    const int bc = (tid & 31) << 2;

    const float* Ap = A + (size_t)(bm + ar) * K + ac;
    const float* Bp = B + (size_t)br * N + bn + bc;

    float acc[2][8][4];
#pragma unroll
    for (int mf = 0; mf < 2; mf++)
#pragma unroll
        for (int nf = 0; nf < 8; nf++)
#pragma unroll
            for (int i = 0; i < 4; i++) acc[mf][nf][i] = 0.f;

    float4 av0 = *(const float4*)(Ap);
    float4 av1 = *(const float4*)(Ap + (size_t)64 * K);
    float4 bv0 = *(const float4*)(Bp);
    float4 bv1 = *(const float4*)(Bp + (size_t)8 * N);

    int buf = 0;
    *(float4*)&As[buf][ar][ac]      = f2tf32x4(av0);
    *(float4*)&As[buf][ar + 64][ac] = f2tf32x4(av1);
    *(float4*)&Bs[buf][br][bc]      = f2tf32x4(bv0);
    *(float4*)&Bs[buf][br + 8][bc]  = f2tf32x4(bv1);
    __syncthreads();

    for (int k0 = 0; k0 < K; k0 += 16) {
        const bool has_next = (k0 + 16) < K;
        if (has_next) {
            av0 = *(const float4*)(Ap + (k0 + 16));
            av1 = *(const float4*)(Ap + (size_t)64 * K + (k0 + 16));
            bv0 = *(const float4*)(Bp + (size_t)(k0 + 16) * N);
            bv1 = *(const float4*)(Bp + (size_t)(k0 + 24) * N);
        }

#pragma unroll
        for (int kk = 0; kk < 16; kk += 8) {
            uint32_t a[2][4];
#pragma unroll
            for (int mf = 0; mf < 2; mf++) {
                const int m = wm + mf * 16 + g;
                a[mf][0] = __float_as_uint(As[buf][m][kk + tig]);
                a[mf][1] = __float_as_uint(As[buf][m + 8][kk + tig]);
                a[mf][2] = __float_as_uint(As[buf][m][kk + tig + 4]);
                a[mf][3] = __float_as_uint(As[buf][m + 8][kk + tig + 4]);
            }
#pragma unroll
            for (int nf = 0; nf < 8; nf++) {
                const int n = wn + nf * 8 + g;
                uint32_t b0 = __float_as_uint(Bs[buf][kk + tig][n]);
                uint32_t b1 = __float_as_uint(Bs[buf][kk + tig + 4][n]);
                mma_tf32(acc[0][nf], a[0], b0, b1);
                mma_tf32(acc[1][nf], a[1], b0, b1);
            }
        }

        if (has_next) {
            const int nb = buf ^ 1;
            *(float4*)&As[nb][ar][ac]      = f2tf32x4(av0);
            *(float4*)&As[nb][ar + 64][ac] = f2tf32x4(av1);
            *(float4*)&Bs[nb][br][bc]      = f2tf32x4(bv0);
            *(float4*)&Bs[nb][br + 8][bc]  = f2tf32x4(bv1);
            __syncthreads();
            buf = nb;
        }
    }

#pragma unroll
    for (int mf = 0; mf < 2; mf++) {
        const int row = bm + wm + mf * 16 + g;
#pragma unroll
        for (int nf = 0; nf < 8; nf++) {
            const int col = bn + wn + nf * 8 + tig * 2;
            *(float2*)&C[(size_t)row * N + col] =
                make_float2(acc[mf][nf][0], acc[mf][nf][1]);
            *(float2*)&C[(size_t)(row + 8) * N + col] =
                make_float2(acc[mf][nf][2], acc[mf][nf][3]);
        }
    }
}

// ---------------------------------------------------------------------------
// beta / g projections, v2: 128 CTAs x 256 threads, K split 4 ways.
// thread = (pos 0..63, kq 0..3); each accumulates 32 outputs over K/4=512.
// ---------------------------------------------------------------------------
__global__ __launch_bounds__(256)
void proj_bg_kernel(const float* __restrict__ hs,
                    const float* __restrict__ Wb, const float* __restrict__ Wa,
                    const float* __restrict__ A_log, const float* __restrict__ dt_bias,
                    float* __restrict__ egp, float* __restrict__ betap) {
    __shared__ __align__(16) float Ws[4][16][32];
    __shared__ float Red[3][64][33];

    const int tid = threadIdx.x;
    const int pos = tid & 63;
    const int kq  = tid >> 6;
    const int p0  = blockIdx.x * 64;

    float acc[32];
#pragma unroll
    for (int c = 0; c < 32; c++) acc[c] = 0.f;

    const float* hp = hs + (size_t)(p0 + pos) * DDIM + kq * 512;

    for (int k0 = 0; k0 < 512; k0 += 16) {
        __syncthreads();
        for (int i = tid; i < 2048; i += 256) {
            int kqi = i >> 9, rem = i & 511;
            int kk = rem >> 5, c = rem & 31;
            int k = kqi * 512 + k0 + kk;
            Ws[kqi][kk][c] = (c < 16) ? Wb[(size_t)k * 16 + c]
                                      : Wa[(size_t)k * 16 + (c - 16)];
        }
        __syncthreads();

        float xr[16];
        *(float4*)(xr)      = *(const float4*)(hp + k0);
        *(float4*)(xr + 4)  = *(const float4*)(hp + k0 + 4);
        *(float4*)(xr + 8)  = *(const float4*)(hp + k0 + 8);
        *(float4*)(xr + 12) = *(const float4*)(hp + k0 + 12);
#pragma unroll
        for (int kk = 0; kk < 16; kk++) {
            float a = xr[kk];
            float wr[32];
#pragma unroll
            for (int c4 = 0; c4 < 8; c4++)
                *(float4*)(wr + 4 * c4) = *(const float4*)(&Ws[kq][kk][4 * c4]);
#pragma unroll
            for (int c = 0; c < 32; c++) acc[c] = fmaf(a, wr[c], acc[c]);
        }
    }

    __syncthreads();
    if (kq) {
#pragma unroll
        for (int c = 0; c < 32; c++) Red[kq - 1][pos][c] = acc[c];
    }
    __syncthreads();
    if (kq == 0) {
#pragma unroll
        for (int c = 0; c < 32; c++)
            acc[c] += Red[0][pos][c] + Red[1][pos][c] + Red[2][pos][c];

        const int p = p0 + pos;
        const int b = p >> 12, s = p & 4095;
#pragma unroll
        for (int h = 0; h < HN; h++) {
            float beta = 1.f / (1.f + expf(-acc[h]));
            float xa = acc[16 + h] + dt_bias[h];
            float sp = (xa > 20.f) ? xa : log1pf(expf(xa));
            float g  = -expf(A_log[h]) * sp;
            float eg = expf(g);
            size_t o = ((size_t)(b * HN + h)) * SDIM + s;
            betap[o] = beta;
            egp[o]   = eg;
        }
    }
}

// ---------------------------------------------------------------------------
// Conv v2: 4 positions per CTA, warp-direct (no smem). 2048 CTAs x 512 thr.
// task t = chunk*4 + pos; chunk 0..47 (q:0-15, k:16-31, v:32-47).
// Each warp handles one (pos, 128-channel chunk): conv+silu, L2-norm for q/k.
// ---------------------------------------------------------------------------
__global__ __launch_bounds__(512)
void conv_kernel(const float* __restrict__ mixed, const float* __restrict__ cw,
                 float* __restrict__ qg, float* __restrict__ kg, float* __restrict__ vg) {
    const int p0 = blockIdx.x * 4;
    const int b  = p0 >> 12;
    const int s0 = p0 & 4095;
    const int w  = threadIdx.x >> 5, lane = threadIdx.x & 31;

    const float4* cw4 = (const float4*)cw;
    const float4* mx4 = (const float4*)mixed;

    for (int t = w; t < 192; t += 16) {
        const int s     = s0 + (t & 3);
        const int chunk = t >> 2;                 // 0..47
        const int ch    = chunk * 128 + lane * 4; // channel base
        const int ch4   = ch >> 2;

        float4 w0 = cw4[ch + 0];
        float4 w1 = cw4[ch + 1];
        float4 w2 = cw4[ch + 2];
        float4 w3 = cw4[ch + 3];

        float4 m[4];
#pragma unroll
        for (int j = 0; j < 4; j++) {
            int ss = s - 3 + j;
            if (ss >= 0) m[j] = mx4[(size_t)(b * SDIM + ss) * (CONVD / 4) + ch4];
            else         m[j] = make_float4(0.f, 0.f, 0.f, 0.f);
        }
        float4 a;
        a.x = fmaf(m[3].x, w0.w, fmaf(m[2].x, w0.z, fmaf(m[1].x, w0.y, m[0].x * w0.x)));
        a.y = fmaf(m[3].y, w1.w, fmaf(m[2].y, w1.z, fmaf(m[1].y, w1.y, m[0].y * w1.x)));
        a.z = fmaf(m[3].z, w2.w, fmaf(m[2].z, w2.z, fmaf(m[1].z, w2.y, m[0].z * w2.x)));
        a.w = fmaf(m[3].w, w3.w, fmaf(m[2].w, w3.z, fmaf(m[1].w, w3.y, m[0].w * w3.x)));
        a.x = a.x / (1.f + expf(-a.x));
        a.y = a.y / (1.f + expf(-a.y));
        a.z = a.z / (1.f + expf(-a.z));
        a.w = a.w / (1.f + expf(-a.w));

        if (chunk < 32) {
            // q or k: per-128-chunk L2 norm (warp-wide reduce)
            float ssq = a.x * a.x;
            ssq = fmaf(a.y, a.y, ssq);
            ssq = fmaf(a.z, a.z, ssq);
            ssq = fmaf(a.w, a.w, ssq);
#pragma unroll
            for (int off = 16; off; off >>= 1)
                ssq += __shfl_xor_sync(0xffffffffu, ssq, off);
            float r = rsqrtf(ssq + EPSF);
            float* dst;
            int hh;
            if (chunk < 16) { r *= 0.08838834764831845f; dst = qg; hh = chunk; }
            else            { dst = kg; hh = chunk - 16; }
            size_t o = ((((size_t)(b * HN + hh)) * SDIM + s) * DKN) + lane * 4;
            *(float4*)(dst + o) = make_float4(a.x * r, a.y * r, a.z * r, a.w * r);
        } else {
            int hh = chunk - 32;
            size_t o = ((((size_t)(b * HN + hh)) * SDIM + s) * DKN) + lane * 4;
            *(float4*)(vg + o) = a;
        }
    }
}

// ---------------------------------------------------------------------------
// Gated delta-rule recurrence, v-split 4 ways, double-buffered chunks.
// CTA = (bh, v-quarter): 128 CTAs, 512 threads.
// thread = (vcol 0..31, k-sixteenth 0..15); state S[8] registers.
// ---------------------------------------------------------------------------
#define RCH 16
__global__ __launch_bounds__(512, 1)
void recur_kernel(const float* __restrict__ qg, const float* __restrict__ kg,
                  const float* __restrict__ vg, const float* __restrict__ egg,
                  const float* __restrict__ btg, float* __restrict__ core) {
    __shared__ __align__(16) float q_sh[2][RCH * 128];
    __shared__ __align__(16) float k_sh[2][RCH * 128];
    __shared__ __align__(16) float v_sh[2][RCH * 32];
    __shared__ float eg_sh[2][RCH], bt_sh[2][RCH], qk_sh[2][RCH];

    const int blk = blockIdx.x;
    const int bh  = blk >> 2;
    const int vq  = blk & 3;
    const int b = bh >> 4, h = bh & 15;

    const float* qp  = qg  + (size_t)bh * SDIM * DKN;
    const float* kp  = kg  + (size_t)bh * SDIM * DKN;
    const float* vp  = vg  + (size_t)bh * SDIM * DKN + vq * 32;
    const float* egp = egg + (size_t)bh * SDIM;
    const float* btp = btg + (size_t)bh * SDIM;

    const int tid  = threadIdx.x;
    const int vcol = tid >> 4;
    const int kq   = tid & 15;
    const int kb   = kq * 8;
    const int lane = tid & 31, w = tid >> 5;

    float S[8];
#pragma unroll
    for (int i = 0; i < 8; i++) S[i] = 0.f;

#define RSTAGE(sel, c0)                                                       \
    do {                                                                      \
        for (int i = tid; i < RCH * 128; i += 512) {                          \
            size_t gi = (size_t)(c0) * 128 + i;                               \
            q_sh[sel][i] = qp[gi];                                            \
            k_sh[sel][i] = kp[gi];                                            \
        }                                                                     \
        for (int i = tid; i < RCH * 32; i += 512) {                           \
            int row = i >> 5, col = i & 31;                                   \
            v_sh[sel][i] = vp[(size_t)((c0) + row) * DKN + col];              \
        }                                                                     \
        if (tid < RCH) {                                                      \
            eg_sh[sel][tid] = egp[(c0) + tid];                                \
            bt_sh[sel][tid] = btp[(c0) + tid];                                \
        }                                                                     \
    } while (0)

    RSTAGE(0, 0);
    __syncthreads();

    const int nch = SDIM / RCH;
    for (int ci = 0; ci < nch; ci++) {
        const int buf = ci & 1;
        // prefetch next chunk (hidden under this chunk's compute)
        if (ci + 1 < nch) RSTAGE(buf ^ 1, (ci + 1) * RCH);

        // per-step q.k (warp w -> step w), reads current buf
        {
            float s = 0.f;
#pragma unroll
            for (int i = 0; i < 4; i++)
                s = fmaf(q_sh[buf][w * 128 + lane + 32 * i],
                         k_sh[buf][w * 128 + lane + 32 * i], s);
#pragma unroll
            for (int off = 16; off; off >>= 1)
                s += __shfl_xor_sync(0xffffffffu, s, off);
            if (lane == 0) qk_sh[buf][w] = s;
        }
        __syncthreads();

#pragma unroll 1
        for (int t = 0; t < RCH; t++) {
            const float eg = eg_sh[buf][t], bt = bt_sh[buf][t], qk = qk_sh[buf][t];
            const float vt = v_sh[buf][t * 32 + vcol];
            const float4* k4 = (const float4*)(k_sh[buf] + t * 128 + kb);
            const float4* q4 = (const float4*)(q_sh[buf] + t * 128 + kb);

            float4 k0 = k4[0], k1 = k4[1];
            float4 q0 = q4[0], q1 = q4[1];

            // two-chain dot products (shorter critical path)
            float pa, pb, qa, qb;
            pa = k0.x * S[0];          pb = k0.z * S[2];
            pa = fmaf(k0.y, S[1], pa); pb = fmaf(k0.w, S[3], pb);
            pa = fmaf(k1.x, S[4], pa); pb = fmaf(k1.z, S[6], pb);
            pa = fmaf(k1.y, S[5], pa); pb = fmaf(k1.w, S[7], pb);
            qa = q0.x * S[0];          qb = q0.z * S[2];
            qa = fmaf(q0.y, S[1], qa); qb = fmaf(q0.w, S[3], qb);
            qa = fmaf(q1.x, S[4], qa); qb = fmaf(q1.z, S[6], qb);
            qa = fmaf(q1.y, S[5], qa); qb = fmaf(q1.w, S[7], qb);
            float pred = pa + pb;
            float qs   = qa + qb;

            pred += __shfl_xor_sync(0xffffffffu, pred, 1);
            qs   += __shfl_xor_sync(0xffffffffu, qs, 1);
            pred += __shfl_xor_sync(0xffffffffu, pred, 2);
            qs   += __shfl_xor_sync(0xffffffffu, qs, 2);
            pred += __shfl_xor_sync(0xffffffffu, pred, 4);
            qs   += __shfl_xor_sync(0xffffffffu, qs, 4);
            pred += __shfl_xor_sync(0xffffffffu, pred, 8);
            qs   += __shfl_xor_sync(0xffffffffu, qs, 8);

            pred *= eg;
            const float delta = (vt - pred) * bt;
            const float o = fmaf(qk, delta, eg * qs);

            S[0] = fmaf(eg, S[0], k0.x * delta);
            S[1] = fmaf(eg, S[1], k0.y * delta);
            S[2] = fmaf(eg, S[2], k0.z * delta);
            S[3] = fmaf(eg, S[3], k0.w * delta);
            S[4] = fmaf(eg, S[4], k1.x * delta);
            S[5] = fmaf(eg, S[5], k1.y * delta);
            S[6] = fmaf(eg, S[6], k1.z * delta);
            S[7] = fmaf(eg, S[7], k1.w * delta);

            if (kq == 0)
                core[((size_t)(b * SDIM + ci * RCH + t) * HN + h) * DKN + vq * 32 + vcol] = o;
        }
        __syncthreads();
    }
#undef RSTAGE
}

// ---------------------------------------------------------------------------
// Gated RMSNorm
// ---------------------------------------------------------------------------
__global__ __launch_bounds__(512)
void rmsgate_kernel(const float* __restrict__ z, const float* __restrict__ nw,
                    float* __restrict__ core) {
    const int p = blockIdx.x;
    const int w = threadIdx.x >> 5, lane = threadIdx.x & 31;
    const size_t base = ((size_t)p * HN + w) * DKN;

    float x[4];
    float ssq = 0.f;
#pragma unroll
    for (int i = 0; i < 4; i++) {
        x[i] = core[base + lane + 32 * i];
        ssq = fmaf(x[i], x[i], ssq);
    }
#pragma unroll
    for (int off = 16; off; off >>= 1)
        ssq += __shfl_xor_sync(0xffffffffu, ssq, off);
    const float r = rsqrtf(ssq * (1.0f / 128.0f) + EPSF);

#pragma unroll
    for (int i = 0; i < 4; i++) {
        int d = lane + 32 * i;
        float zz  = z[(size_t)p * VALD + w * DKN + d];
        float sil = zz / (1.f + expf(-zz));
        core[base + d] = x[i] * r * nw[d] * sil;
    }
}

// ---------------------------------------------------------------------------
extern "C" void kernel_launch(void* const* d_in, const int* in_sizes, int n_in,
                              void* d_out, int out_size) {
    const float* hs      = (const float*)d_in[0];
    const float* W_qkv   = (const float*)d_in[1];
    const float* W_z     = (const float*)d_in[2];
    const float* W_b     = (const float*)d_in[3];
    const float* W_a     = (const float*)d_in[4];
    const float* conv_w  = (const float*)d_in[5];
    const float* A_log   = (const float*)d_in[6];
    const float* dt_bias = (const float*)d_in[7];
    const float* norm_w  = (const float*)d_in[8];
    const float* W_out   = (const float*)d_in[9];
    float* out = (float*)d_out;

    float* scratch = nullptr;
    cudaGetSymbolAddress((void**)&scratch, g_scratch);
    float* mixed = scratch + OFF_MIXED;
    float* zb    = scratch + OFF_Z;
    float* qb    = scratch + OFF_Q;
    float* kb    = scratch + OFF_K;
    float* vb    = scratch + OFF_V;
    float* coreb = scratch + OFF_CORE;
    float* egb   = scratch + OFF_EG;
    float* betab = scratch + OFF_BETA;

    // 1) mixed = hs @ W_qkv   [8192 x 6144]  (TF32 warp-MMA)
    gemm_tf32_kernel<<<dim3(CONVD / 128, NPOS / 128), 256>>>(hs, W_qkv, mixed, NPOS, CONVD, DDIM);
    // 2) z = hs @ W_z         [8192 x 2048]
    gemm_tf32_kernel<<<dim3(VALD / 128, NPOS / 128), 256>>>(hs, W_z, zb, NPOS, VALD, DDIM);
    // 3) beta / exp(g)  (K split 4 ways, 128 CTAs)
    proj_bg_kernel<<<NPOS / 64, 256>>>(hs, W_b, W_a, A_log, dt_bias, egb, betab);
    // 4) conv + silu + l2norm -> q,k,v  (4 positions per CTA, warp-direct)
    conv_kernel<<<NPOS / 4, 512>>>(mixed, conv_w, qb, kb, vb);
    // 5) gated delta recurrence -> core (v split 4x, double-buffered)
    recur_kernel<<<BDIM * HN * 4, 512>>>(qb, kb, vb, egb, betab, coreb);
    // 6) gated RMSNorm (in place)
    rmsgate_kernel<<<NPOS, 512>>>(zb, norm_w, coreb);
    // 7) out = core @ W_out
    gemm_tf32_kernel<<<dim3(DDIM / 128, NPOS / 128), 256>>>(coreb, W_out, out, NPOS, DDIM, VALD);
}

// round 17
// speedup vs baseline: 1.0057x; 1.0057x over previous
#include <cuda_runtime.h>
#include <cuda_bf16.h>
#include <math.h>
#include <stdint.h>

// ---------------------------------------------------------------------------
// GatedDeltaNet forward, GB300 (sm_103a bench; legacy PTX target => warp MMA).
// GEMMs: TF32 m16n8k8 (R12 proven, HMMA rate-capped). Non-GEMM kernels tuned.
// Shapes: B=2, S=4096, D=2048, H=16, DK=DV=128, CONV_DIM=6144, KCONV=4
// ---------------------------------------------------------------------------

#define BDIM   2
#define SDIM   4096
#define DDIM   2048
#define HN     16
#define DKN    128
#define CONVD  6144
#define KEYD   2048
#define VALD   2048
#define NPOS   (BDIM*SDIM)        // 8192
#define EPSF   1e-6f

// ---- scratch (device global; allocation-free) ----
#define OFF_MIXED 0
#define OFF_Z     50331648
#define OFF_Q     67108864
#define OFF_K     83886080
#define OFF_V     100663296
#define OFF_CORE  117440512
#define OFF_EG    134217728
#define OFF_BETA  134348800
#define SCRATCH_TOTAL 134479872

__device__ float g_scratch[SCRATCH_TOTAL];

// ---------------------------------------------------------------------------
// TF32 helpers
// ---------------------------------------------------------------------------
__device__ __forceinline__ float f2tf32(float x) {
    uint32_t u;
    asm("cvt.rna.tf32.f32 %0, %1;" : "=r"(u) : "f"(x));
    return __uint_as_float(u);
}
__device__ __forceinline__ float4 f2tf32x4(float4 v) {
    return make_float4(f2tf32(v.x), f2tf32(v.y), f2tf32(v.z), f2tf32(v.w));
}
__device__ __forceinline__ void mma_tf32(float* c, const uint32_t* a,
                                         uint32_t b0, uint32_t b1) {
    asm volatile(
        "mma.sync.aligned.m16n8k8.row.col.f32.tf32.tf32.f32 "
        "{%0,%1,%2,%3}, {%4,%5,%6,%7}, {%8,%9}, {%0,%1,%2,%3};"
        : "+f"(c[0]), "+f"(c[1]), "+f"(c[2]), "+f"(c[3])
        : "r"(a[0]), "r"(a[1]), "r"(a[2]), "r"(a[3]), "r"(b0), "r"(b1));
}

// ---------------------------------------------------------------------------
// TF32 GEMM (verbatim from R12, best known): 128x128 tile, BK=16, 256 thr.
// ---------------------------------------------------------------------------
__global__ __launch_bounds__(256, 2)
void gemm_tf32_kernel(const float* __restrict__ A, const float* __restrict__ B,
                      float* __restrict__ C, int M, int N, int K) {
    __shared__ __align__(16) float As[2][128][20];
    __shared__ __align__(16) float Bs[2][16][136];

    const int tid  = threadIdx.x;
    const int bm   = blockIdx.y * 128;
    const int bn   = blockIdx.x * 128;

    const int warp = tid >> 5, lane = tid & 31;
    const int wm = (warp & 3) * 32;
    const int wn = (warp >> 2) * 64;
    const int g  = lane >> 2;
    const int tig = lane & 3;

    const int ar = tid >> 2;
    const int ac = (tid & 3) << 2;
    const int br = tid >> 5;
    const int bc = (tid & 31) << 2;

    const float* Ap = A + (size_t)(bm + ar) * K + ac;
    const float* Bp = B + (size_t)br * N + bn + bc;

    float acc[2][8][4];
#pragma unroll
    for (int mf = 0; mf < 2; mf++)
#pragma unroll
        for (int nf = 0; nf < 8; nf++)
#pragma unroll
            for (int i = 0; i < 4; i++) acc[mf][nf][i] = 0.f;

    float4 av0 = *(const float4*)(Ap);
    float4 av1 = *(const float4*)(Ap + (size_t)64 * K);
    float4 bv0 = *(const float4*)(Bp);
    float4 bv1 = *(const float4*)(Bp + (size_t)8 * N);

    int buf = 0;
    *(float4*)&As[buf][ar][ac]      = f2tf32x4(av0);
    *(float4*)&As[buf][ar + 64][ac] = f2tf32x4(av1);
    *(float4*)&Bs[buf][br][bc]      = f2tf32x4(bv0);
    *(float4*)&Bs[buf][br + 8][bc]  = f2tf32x4(bv1);
    __syncthreads();

    for (int k0 = 0; k0 < K; k0 += 16) {
        const bool has_next = (k0 + 16) < K;
        if (has_next) {
            av0 = *(const float4*)(Ap + (k0 + 16));
            av1 = *(const float4*)(Ap + (size_t)64 * K + (k0 + 16));
            bv0 = *(const float4*)(Bp + (size_t)(k0 + 16) * N);
            bv1 = *(const float4*)(Bp + (size_t)(k0 + 24) * N);
        }

#pragma unroll
        for (int kk = 0; kk < 16; kk += 8) {
            uint32_t a[2][4];
#pragma unroll
            for (int mf = 0; mf < 2; mf++) {
                const int m = wm + mf * 16 + g;
                a[mf][0] = __float_as_uint(As[buf][m][kk + tig]);
                a[mf][1] = __float_as_uint(As[buf][m + 8][kk + tig]);
                a[mf][2] = __float_as_uint(As[buf][m][kk + tig + 4]);
                a[mf][3] = __float_as_uint(As[buf][m + 8][kk + tig + 4]);
            }
#pragma unroll
            for (int nf = 0; nf < 8; nf++) {
                const int n = wn + nf * 8 + g;
                uint32_t b0 = __float_as_uint(Bs[buf][kk + tig][n]);
                uint32_t b1 = __float_as_uint(Bs[buf][kk + tig + 4][n]);
                mma_tf32(acc[0][nf], a[0], b0, b1);
                mma_tf32(acc[1][nf], a[1], b0, b1);
            }
        }

        if (has_next) {
            const int nb = buf ^ 1;
            *(float4*)&As[nb][ar][ac]      = f2tf32x4(av0);
            *(float4*)&As[nb][ar + 64][ac] = f2tf32x4(av1);
            *(float4*)&Bs[nb][br][bc]      = f2tf32x4(bv0);
            *(float4*)&Bs[nb][br + 8][bc]  = f2tf32x4(bv1);
            __syncthreads();
            buf = nb;
        }
    }

#pragma unroll
    for (int mf = 0; mf < 2; mf++) {
        const int row = bm + wm + mf * 16 + g;
#pragma unroll
        for (int nf = 0; nf < 8; nf++) {
            const int col = bn + wn + nf * 8 + tig * 2;
            *(float2*)&C[(size_t)row * N + col] =
                make_float2(acc[mf][nf][0], acc[mf][nf][1]);
            *(float2*)&C[(size_t)(row + 8) * N + col] =
                make_float2(acc[mf][nf][2], acc[mf][nf][3]);
        }
    }
}

// ---------------------------------------------------------------------------
// beta / g projections, v2: 128 CTAs x 256 threads, K split 4 ways.
// thread = (pos 0..63, kq 0..3); each accumulates 32 outputs over K/4=512.
// ---------------------------------------------------------------------------
__global__ __launch_bounds__(256)
void proj_bg_kernel(const float* __restrict__ hs,
                    const float* __restrict__ Wb, const float* __restrict__ Wa,
                    const float* __restrict__ A_log, const float* __restrict__ dt_bias,
                    float* __restrict__ egp, float* __restrict__ betap) {
    __shared__ __align__(16) float Ws[4][16][32];
    __shared__ float Red[3][64][33];

    const int tid = threadIdx.x;
    const int pos = tid & 63;
    const int kq  = tid >> 6;
    const int p0  = blockIdx.x * 64;

    float acc[32];
#pragma unroll
    for (int c = 0; c < 32; c++) acc[c] = 0.f;

    const float* hp = hs + (size_t)(p0 + pos) * DDIM + kq * 512;

    for (int k0 = 0; k0 < 512; k0 += 16) {
        __syncthreads();
        for (int i = tid; i < 2048; i += 256) {
            int kqi = i >> 9, rem = i & 511;
            int kk = rem >> 5, c = rem & 31;
            int k = kqi * 512 + k0 + kk;
            Ws[kqi][kk][c] = (c < 16) ? Wb[(size_t)k * 16 + c]
                                      : Wa[(size_t)k * 16 + (c - 16)];
        }
        __syncthreads();

        float xr[16];
        *(float4*)(xr)      = *(const float4*)(hp + k0);
        *(float4*)(xr + 4)  = *(const float4*)(hp + k0 + 4);
        *(float4*)(xr + 8)  = *(const float4*)(hp + k0 + 8);
        *(float4*)(xr + 12) = *(const float4*)(hp + k0 + 12);
#pragma unroll
        for (int kk = 0; kk < 16; kk++) {
            float a = xr[kk];
            float wr[32];
#pragma unroll
            for (int c4 = 0; c4 < 8; c4++)
                *(float4*)(wr + 4 * c4) = *(const float4*)(&Ws[kq][kk][4 * c4]);
#pragma unroll
            for (int c = 0; c < 32; c++) acc[c] = fmaf(a, wr[c], acc[c]);
        }
    }

    __syncthreads();
    if (kq) {
#pragma unroll
        for (int c = 0; c < 32; c++) Red[kq - 1][pos][c] = acc[c];
    }
    __syncthreads();
    if (kq == 0) {
#pragma unroll
        for (int c = 0; c < 32; c++)
            acc[c] += Red[0][pos][c] + Red[1][pos][c] + Red[2][pos][c];

        const int p = p0 + pos;
        const int b = p >> 12, s = p & 4095;
#pragma unroll
        for (int h = 0; h < HN; h++) {
            float beta = 1.f / (1.f + expf(-acc[h]));
            float xa = acc[16 + h] + dt_bias[h];
            float sp = (xa > 20.f) ? xa : log1pf(expf(xa));
            float g  = -expf(A_log[h]) * sp;
            float eg = expf(g);
            size_t o = ((size_t)(b * HN + h)) * SDIM + s;
            betap[o] = beta;
            egp[o]   = eg;
        }
    }
}

// ---------------------------------------------------------------------------
// Conv v2: 4 positions per CTA, warp-direct (no smem). 2048 CTAs x 512 thr.
// task t = chunk*4 + pos; chunk 0..47 (q:0-15, k:16-31, v:32-47).
// Each warp handles one (pos, 128-channel chunk): conv+silu, L2-norm for q/k.
// ---------------------------------------------------------------------------
__global__ __launch_bounds__(512)
void conv_kernel(const float* __restrict__ mixed, const float* __restrict__ cw,
                 float* __restrict__ qg, float* __restrict__ kg, float* __restrict__ vg) {
    const int p0 = blockIdx.x * 4;
    const int b  = p0 >> 12;
    const int s0 = p0 & 4095;
    const int w  = threadIdx.x >> 5, lane = threadIdx.x & 31;

    const float4* cw4 = (const float4*)cw;
    const float4* mx4 = (const float4*)mixed;

    for (int t = w; t < 192; t += 16) {
        const int s     = s0 + (t & 3);
        const int chunk = t >> 2;                 // 0..47
        const int ch    = chunk * 128 + lane * 4; // channel base
        const int ch4   = ch >> 2;

        float4 w0 = cw4[ch + 0];
        float4 w1 = cw4[ch + 1];
        float4 w2 = cw4[ch + 2];
        float4 w3 = cw4[ch + 3];

        float4 m[4];
#pragma unroll
        for (int j = 0; j < 4; j++) {
            int ss = s - 3 + j;
            if (ss >= 0) m[j] = mx4[(size_t)(b * SDIM + ss) * (CONVD / 4) + ch4];
            else         m[j] = make_float4(0.f, 0.f, 0.f, 0.f);
        }
        float4 a;
        a.x = fmaf(m[3].x, w0.w, fmaf(m[2].x, w0.z, fmaf(m[1].x, w0.y, m[0].x * w0.x)));
        a.y = fmaf(m[3].y, w1.w, fmaf(m[2].y, w1.z, fmaf(m[1].y, w1.y, m[0].y * w1.x)));
        a.z = fmaf(m[3].z, w2.w, fmaf(m[2].z, w2.z, fmaf(m[1].z, w2.y, m[0].z * w2.x)));
        a.w = fmaf(m[3].w, w3.w, fmaf(m[2].w, w3.z, fmaf(m[1].w, w3.y, m[0].w * w3.x)));
        a.x = a.x / (1.f + expf(-a.x));
        a.y = a.y / (1.f + expf(-a.y));
        a.z = a.z / (1.f + expf(-a.z));
        a.w = a.w / (1.f + expf(-a.w));

        if (chunk < 32) {
            // q or k: per-128-chunk L2 norm (warp-wide reduce)
            float ssq = a.x * a.x;
            ssq = fmaf(a.y, a.y, ssq);
            ssq = fmaf(a.z, a.z, ssq);
            ssq = fmaf(a.w, a.w, ssq);
#pragma unroll
            for (int off = 16; off; off >>= 1)
                ssq += __shfl_xor_sync(0xffffffffu, ssq, off);
            float r = rsqrtf(ssq + EPSF);
            float* dst;
            int hh;
            if (chunk < 16) { r *= 0.08838834764831845f; dst = qg; hh = chunk; }
            else            { dst = kg; hh = chunk - 16; }
            size_t o = ((((size_t)(b * HN + hh)) * SDIM + s) * DKN) + lane * 4;
            *(float4*)(dst + o) = make_float4(a.x * r, a.y * r, a.z * r, a.w * r);
        } else {
            int hh = chunk - 32;
            size_t o = ((((size_t)(b * HN + hh)) * SDIM + s) * DKN) + lane * 4;
            *(float4*)(vg + o) = a;
        }
    }
}

// ---------------------------------------------------------------------------
// Gated delta-rule recurrence, v-split 4 ways, double-buffered chunks.
// CTA = (bh, v-quarter): 128 CTAs, 512 threads.
// thread = (vcol 0..31, k-sixteenth 0..15); state S[8] registers.
// ---------------------------------------------------------------------------
#define RCH 16
__global__ __launch_bounds__(512, 1)
void recur_kernel(const float* __restrict__ qg, const float* __restrict__ kg,
                  const float* __restrict__ vg, const float* __restrict__ egg,
                  const float* __restrict__ btg, float* __restrict__ core) {
    __shared__ __align__(16) float q_sh[2][RCH * 128];
    __shared__ __align__(16) float k_sh[2][RCH * 128];
    __shared__ __align__(16) float v_sh[2][RCH * 32];
    __shared__ float eg_sh[2][RCH], bt_sh[2][RCH], qk_sh[2][RCH];

    const int blk = blockIdx.x;
    const int bh  = blk >> 2;
    const int vq  = blk & 3;
    const int b = bh >> 4, h = bh & 15;

    const float* qp  = qg  + (size_t)bh * SDIM * DKN;
    const float* kp  = kg  + (size_t)bh * SDIM * DKN;
    const float* vp  = vg  + (size_t)bh * SDIM * DKN + vq * 32;
    const float* egp = egg + (size_t)bh * SDIM;
    const float* btp = btg + (size_t)bh * SDIM;

    const int tid  = threadIdx.x;
    const int vcol = tid >> 4;
    const int kq   = tid & 15;
    const int kb   = kq * 8;
    const int lane = tid & 31, w = tid >> 5;

    float S[8];
#pragma unroll
    for (int i = 0; i < 8; i++) S[i] = 0.f;

#define RSTAGE(sel, c0)                                                       \
    do {                                                                      \
        for (int i = tid; i < RCH * 128; i += 512) {                          \
            size_t gi = (size_t)(c0) * 128 + i;                               \
            q_sh[sel][i] = qp[gi];                                            \
            k_sh[sel][i] = kp[gi];                                            \
        }                                                                     \
        for (int i = tid; i < RCH * 32; i += 512) {                           \
            int row = i >> 5, col = i & 31;                                   \
            v_sh[sel][i] = vp[(size_t)((c0) + row) * DKN + col];              \
        }                                                                     \
        if (tid < RCH) {                                                      \
            eg_sh[sel][tid] = egp[(c0) + tid];                                \
            bt_sh[sel][tid] = btp[(c0) + tid];                                \
        }                                                                     \
    } while (0)

    RSTAGE(0, 0);
    __syncthreads();

    const int nch = SDIM / RCH;
    for (int ci = 0; ci < nch; ci++) {
        const int buf = ci & 1;
        // prefetch next chunk (hidden under this chunk's compute)
        if (ci + 1 < nch) RSTAGE(buf ^ 1, (ci + 1) * RCH);

        // per-step q.k (warp w -> step w), reads current buf
        {
            float s = 0.f;
#pragma unroll
            for (int i = 0; i < 4; i++)
                s = fmaf(q_sh[buf][w * 128 + lane + 32 * i],
                         k_sh[buf][w * 128 + lane + 32 * i], s);
#pragma unroll
            for (int off = 16; off; off >>= 1)
                s += __shfl_xor_sync(0xffffffffu, s, off);
            if (lane == 0) qk_sh[buf][w] = s;
        }
        __syncthreads();

#pragma unroll 1
        for (int t = 0; t < RCH; t++) {
            const float eg = eg_sh[buf][t], bt = bt_sh[buf][t], qk = qk_sh[buf][t];
            const float vt = v_sh[buf][t * 32 + vcol];
            const float4* k4 = (const float4*)(k_sh[buf] + t * 128 + kb);
            const float4* q4 = (const float4*)(q_sh[buf] + t * 128 + kb);

            float4 k0 = k4[0], k1 = k4[1];
            float4 q0 = q4[0], q1 = q4[1];

            // two-chain dot products (shorter critical path)
            float pa, pb, qa, qb;
            pa = k0.x * S[0];          pb = k0.z * S[2];
            pa = fmaf(k0.y, S[1], pa); pb = fmaf(k0.w, S[3], pb);
            pa = fmaf(k1.x, S[4], pa); pb = fmaf(k1.z, S[6], pb);
            pa = fmaf(k1.y, S[5], pa); pb = fmaf(k1.w, S[7], pb);
            qa = q0.x * S[0];          qb = q0.z * S[2];
            qa = fmaf(q0.y, S[1], qa); qb = fmaf(q0.w, S[3], qb);
            qa = fmaf(q1.x, S[4], qa); qb = fmaf(q1.z, S[6], qb);
            qa = fmaf(q1.y, S[5], qa); qb = fmaf(q1.w, S[7], qb);
            float pred = pa + pb;
            float qs   = qa + qb;

            pred += __shfl_xor_sync(0xffffffffu, pred, 1);
            qs   += __shfl_xor_sync(0xffffffffu, qs, 1);
            pred += __shfl_xor_sync(0xffffffffu, pred, 2);
            qs   += __shfl_xor_sync(0xffffffffu, qs, 2);
            pred += __shfl_xor_sync(0xffffffffu, pred, 4);
            qs   += __shfl_xor_sync(0xffffffffu, qs, 4);
            pred += __shfl_xor_sync(0xffffffffu, pred, 8);
            qs   += __shfl_xor_sync(0xffffffffu, qs, 8);

            pred *= eg;
            const float delta = (vt - pred) * bt;
            const float o = fmaf(qk, delta, eg * qs);

            S[0] = fmaf(eg, S[0], k0.x * delta);
            S[1] = fmaf(eg, S[1], k0.y * delta);
            S[2] = fmaf(eg, S[2], k0.z * delta);
            S[3] = fmaf(eg, S[3], k0.w * delta);
            S[4] = fmaf(eg, S[4], k1.x * delta);
            S[5] = fmaf(eg, S[5], k1.y * delta);
            S[6] = fmaf(eg, S[6], k1.z * delta);
            S[7] = fmaf(eg, S[7], k1.w * delta);

            if (kq == 0)
                core[((size_t)(b * SDIM + ci * RCH + t) * HN + h) * DKN + vq * 32 + vcol] = o;
        }
        __syncthreads();
    }
#undef RSTAGE
}

// ---------------------------------------------------------------------------
// Gated RMSNorm
// ---------------------------------------------------------------------------
__global__ __launch_bounds__(512)
void rmsgate_kernel(const float* __restrict__ z, const float* __restrict__ nw,
                    float* __restrict__ core) {
    const int p = blockIdx.x;
    const int w = threadIdx.x >> 5, lane = threadIdx.x & 31;
    const size_t base = ((size_t)p * HN + w) * DKN;

    float x[4];
    float ssq = 0.f;
#pragma unroll
    for (int i = 0; i < 4; i++) {
        x[i] = core[base + lane + 32 * i];
        ssq = fmaf(x[i], x[i], ssq);
    }
#pragma unroll
    for (int off = 16; off; off >>= 1)
        ssq += __shfl_xor_sync(0xffffffffu, ssq, off);
    const float r = rsqrtf(ssq * (1.0f / 128.0f) + EPSF);

#pragma unroll
    for (int i = 0; i < 4; i++) {
        int d = lane + 32 * i;
        float zz  = z[(size_t)p * VALD + w * DKN + d];
        float sil = zz / (1.f + expf(-zz));
        core[base + d] = x[i] * r * nw[d] * sil;
    }
}

// ---------------------------------------------------------------------------
extern "C" void kernel_launch(void* const* d_in, const int* in_sizes, int n_in,
                              void* d_out, int out_size) {
    const float* hs      = (const float*)d_in[0];
    const float* W_qkv   = (const float*)d_in[1];
    const float* W_z     = (const float*)d_in[2];
    const float* W_b     = (const float*)d_in[3];
    const float* W_a     = (const float*)d_in[4];
    const float* conv_w  = (const float*)d_in[5];
    const float* A_log   = (const float*)d_in[6];
    const float* dt_bias = (const float*)d_in[7];
    const float* norm_w  = (const float*)d_in[8];
    const float* W_out   = (const float*)d_in[9];
    float* out = (float*)d_out;

    float* scratch = nullptr;
    cudaGetSymbolAddress((void**)&scratch, g_scratch);
    float* mixed = scratch + OFF_MIXED;
    float* zb    = scratch + OFF_Z;
    float* qb    = scratch + OFF_Q;
    float* kb    = scratch + OFF_K;
    float* vb    = scratch + OFF_V;
    float* coreb = scratch + OFF_CORE;
    float* egb   = scratch + OFF_EG;
    float* betab = scratch + OFF_BETA;

    // 1) mixed = hs @ W_qkv   [8192 x 6144]  (TF32 warp-MMA)
    gemm_tf32_kernel<<<dim3(CONVD / 128, NPOS / 128), 256>>>(hs, W_qkv, mixed, NPOS, CONVD, DDIM);
    // 2) z = hs @ W_z         [8192 x 2048]
    gemm_tf32_kernel<<<dim3(VALD / 128, NPOS / 128), 256>>>(hs, W_z, zb, NPOS, VALD, DDIM);
    // 3) beta / exp(g)  (K split 4 ways, 128 CTAs)
    proj_bg_kernel<<<NPOS / 64, 256>>>(hs, W_b, W_a, A_log, dt_bias, egb, betab);
    // 4) conv + silu + l2norm -> q,k,v  (4 positions per CTA, warp-direct)
    conv_kernel<<<NPOS / 4, 512>>>(mixed, conv_w, qb, kb, vb);
    // 5) gated delta recurrence -> core (v split 4x, double-buffered)
    recur_kernel<<<BDIM * HN * 4, 512>>>(qb, kb, vb, egb, betab, coreb);
    // 6) gated RMSNorm (in place)
    rmsgate_kernel<<<NPOS, 512>>>(zb, norm_w, coreb);
    // 7) out = core @ W_out
    gemm_tf32_kernel<<<dim3(DDIM / 128, NPOS / 128), 256>>>(coreb, W_out, out, NPOS, DDIM, VALD);
}